// round 1
// baseline (speedup 1.0000x reference)
#include <cuda_runtime.h>

#define BB 4
#define QQ 256
#define VV 2048
#define HH 512
#define UU 128
#define QB 4

// Scratch (device globals: allocation-free rule)
__device__ float g_pq[BB * QQ * UU];     // [B,Q,U]
__device__ float g_pv[BB * VV * UU];     // [B,V,U]
__device__ float g_attn[BB * QQ * VV];   // [B,Q,V]

__device__ __forceinline__ float ftanh(float x) {
    float y;
    asm("tanh.approx.f32 %0, %1;" : "=f"(y) : "f"(x));
    return y;
}

// ---------------------------------------------------------------------------
// Kernel A: projections. One launch covers both GEMMs:
//   blocks [0,128):  pv = values[B*V,H] @ w2[H,U]
//   blocks [128,144): pq = queries[B*Q,H] @ w1[H,U]
// Tile: BM=64, BN=128(=U), BK=32. 256 threads, 8x4 register tile per thread.
// ---------------------------------------------------------------------------
__global__ __launch_bounds__(256) void proj_kernel(
    const float* __restrict__ queries, const float* __restrict__ values,
    const float* __restrict__ w1, const float* __restrict__ w2)
{
    __shared__ float  as_s[32 * 68];       // A tile transposed [k][m], pad 68
    __shared__ float4 ws4[32 * 32];        // W tile [k][n], 32 x 128 floats

    const float* A; const float* W; float* C; int mbase;
    if (blockIdx.x < 128) { A = values;  W = w2; C = g_pv; mbase = blockIdx.x * 64; }
    else                  { A = queries; W = w1; C = g_pq; mbase = (blockIdx.x - 128) * 64; }

    const int tid = threadIdx.x;
    const int tx = tid & 31;     // n-group: cols tx*4 .. tx*4+3
    const int ty = tid >> 5;     // m-group: rows ty*8 .. ty*8+7

    float acc[8][4];
#pragma unroll
    for (int j = 0; j < 8; j++)
#pragma unroll
        for (int c = 0; c < 4; c++) acc[j][c] = 0.f;

    const float4* A4 = (const float4*)A;
    const float4* W4 = (const float4*)W;

    for (int kt = 0; kt < HH; kt += 32) {
        // Load A tile 64x32 (transposed store)
#pragma unroll
        for (int i = 0; i < 2; i++) {
            int f = tid + i * 256;          // 512 float4
            int m = f >> 3, k4 = f & 7;
            float4 a = A4[(size_t)(mbase + m) * (HH / 4) + (kt >> 2) + k4];
            as_s[(k4 * 4 + 0) * 68 + m] = a.x;
            as_s[(k4 * 4 + 1) * 68 + m] = a.y;
            as_s[(k4 * 4 + 2) * 68 + m] = a.z;
            as_s[(k4 * 4 + 3) * 68 + m] = a.w;
        }
        // Load W tile 32x128
#pragma unroll
        for (int i = 0; i < 4; i++) {
            int f = tid + i * 256;          // 1024 float4
            int k = f >> 5, n4 = f & 31;
            ws4[k * 32 + n4] = W4[(size_t)(kt + k) * (UU / 4) + n4];
        }
        __syncthreads();

        const float4* as4 = (const float4*)as_s;
#pragma unroll
        for (int kk = 0; kk < 32; kk++) {
            float4 a0 = as4[kk * 17 + ty * 2];
            float4 a1 = as4[kk * 17 + ty * 2 + 1];
            float4 b  = ws4[kk * 32 + tx];
            float av[8] = {a0.x, a0.y, a0.z, a0.w, a1.x, a1.y, a1.z, a1.w};
#pragma unroll
            for (int j = 0; j < 8; j++) {
                acc[j][0] += av[j] * b.x;
                acc[j][1] += av[j] * b.y;
                acc[j][2] += av[j] * b.z;
                acc[j][3] += av[j] * b.w;
            }
        }
        __syncthreads();
    }

    float4* C4 = (float4*)C;
#pragma unroll
    for (int j = 0; j < 8; j++) {
        float4 o;
        o.x = acc[j][0]; o.y = acc[j][1]; o.z = acc[j][2]; o.w = acc[j][3];
        C4[(size_t)(mbase + ty * 8 + j) * (UU / 4) + tx] = o;
    }
}

// ---------------------------------------------------------------------------
// Kernel B: scores + softmax -> attn.
// Grid = B * (Q/QB) = 256 CTAs, 256 threads. Each CTA: (b, 4 consecutive q).
// pv staged in SMEM tiles of 64 rows x 128 u (reused across the 4 q's).
// Thread t: row r = t&63, u-quarter uq = t>>6 (32 u's). Partials reduced in
// SMEM by threads 0..63. Scores (4x2048) live in SMEM; softmax at the end.
// Dynamic SMEM = 73,216 B.
// ---------------------------------------------------------------------------
__global__ __launch_bounds__(256) void score_kernel(const float* __restrict__ vvec)
{
    extern __shared__ float4 sm4[];
    float4* pvs4 = sm4;                       // 64*33 = 2112 f4 (row stride 33)
    float4* pqs4 = sm4 + 2112;                // 128 f4  (QB x 128 floats)
    float4* vs4  = sm4 + 2112 + 128;          // 32 f4   (v vector)
    float*  scores = (float*)(sm4 + 2112 + 128 + 32);        // 4*2048 floats
    float*  sp     = (float*)(sm4 + 2112 + 128 + 32 + 2048); // 1024 floats

    const int tid = threadIdx.x;
    const int b  = blockIdx.x >> 6;
    const int q0 = (blockIdx.x & 63) * QB;

    // Stage pq rows for the 4 q's and the v vector
    {
        const float* pqg = g_pq + (size_t)(b * QQ + q0) * UU;
        float* pqs = (float*)pqs4;
        for (int i = tid; i < QB * UU; i += 256) pqs[i] = pqg[i];
        float* vsf = (float*)vs4;
        if (tid < UU) vsf[tid] = vvec[tid];
    }
    __syncthreads();

    const float4* pv4 = (const float4*)g_pv;
    const int r  = tid & 63;
    const int uq = tid >> 6;

    for (int vt = 0; vt < VV; vt += 64) {
        // Stage pv tile: 64 rows x 128 floats (2048 float4)
#pragma unroll
        for (int i = 0; i < 8; i++) {
            int f = tid + i * 256;
            int rr = f >> 5, c = f & 31;
            pvs4[rr * 33 + c] = pv4[(size_t)(b * VV + vt + rr) * 32 + c];
        }
        __syncthreads();

        float acc0 = 0.f, acc1 = 0.f, acc2 = 0.f, acc3 = 0.f;
        const float4* prow = pvs4 + r * 33 + uq * 8;
        const float4* pq0  = pqs4 + uq * 8;
        const float4* vv0  = vs4 + uq * 8;

#pragma unroll
        for (int u4 = 0; u4 < 8; u4++) {
            float4 p = prow[u4];
            float4 w = vv0[u4];
            float4 q;
            q = pq0[u4];
            acc0 += ftanh(q.x + p.x) * w.x; acc0 += ftanh(q.y + p.y) * w.y;
            acc0 += ftanh(q.z + p.z) * w.z; acc0 += ftanh(q.w + p.w) * w.w;
            q = pq0[32 + u4];
            acc1 += ftanh(q.x + p.x) * w.x; acc1 += ftanh(q.y + p.y) * w.y;
            acc1 += ftanh(q.z + p.z) * w.z; acc1 += ftanh(q.w + p.w) * w.w;
            q = pq0[64 + u4];
            acc2 += ftanh(q.x + p.x) * w.x; acc2 += ftanh(q.y + p.y) * w.y;
            acc2 += ftanh(q.z + p.z) * w.z; acc2 += ftanh(q.w + p.w) * w.w;
            q = pq0[96 + u4];
            acc3 += ftanh(q.x + p.x) * w.x; acc3 += ftanh(q.y + p.y) * w.y;
            acc3 += ftanh(q.z + p.z) * w.z; acc3 += ftanh(q.w + p.w) * w.w;
        }
        sp[0 * 256 + tid] = acc0;
        sp[1 * 256 + tid] = acc1;
        sp[2 * 256 + tid] = acc2;
        sp[3 * 256 + tid] = acc3;
        __syncthreads();

        if (tid < 64) {
#pragma unroll
            for (int qi = 0; qi < QB; qi++) {
                float s = sp[qi * 256 + tid] + sp[qi * 256 + tid + 64] +
                          sp[qi * 256 + tid + 128] + sp[qi * 256 + tid + 192];
                scores[qi * VV + vt + tid] = s;
            }
        }
        __syncthreads();
    }

    // Softmax over V per q, write normalized attn to global
    float* red = sp;
    for (int qi = 0; qi < QB; qi++) {
        float* sc = scores + qi * VV;

        float m = -1e30f;
        for (int i = tid; i < VV; i += 256) m = fmaxf(m, sc[i]);
        red[tid] = m;
        __syncthreads();
        for (int s = 128; s > 0; s >>= 1) {
            if (tid < s) red[tid] = fmaxf(red[tid], red[tid + s]);
            __syncthreads();
        }
        m = red[0];
        __syncthreads();

        float lsum = 0.f;
        for (int i = tid; i < VV; i += 256) {
            float e = __expf(sc[i] - m);
            sc[i] = e;
            lsum += e;
        }
        red[tid] = lsum;
        __syncthreads();
        for (int s = 128; s > 0; s >>= 1) {
            if (tid < s) red[tid] += red[tid + s];
            __syncthreads();
        }
        float inv = 1.f / red[0];
        __syncthreads();

        float* ag = g_attn + (size_t)(b * QQ + q0 + qi) * VV;
        for (int i = tid; i < VV; i += 256) ag[i] = sc[i] * inv;
    }
}

// ---------------------------------------------------------------------------
// Kernel C: out[b] = attn[b] (256x2048) @ values[b] (2048x512).
// Tile: BM=64, BN=64, BK=32. 256 threads, 4x4 register tile.
// Grid: (H/64=8, Q/64=4, B=4) = 128 CTAs.
// ---------------------------------------------------------------------------
__global__ __launch_bounds__(256) void av_kernel(
    const float* __restrict__ values, float* __restrict__ out)
{
    __shared__ float  as_s[32 * 68];   // attn tile transposed [k][m]
    __shared__ float4 bs4[32 * 16];    // values tile [k][n], 32 x 64 floats

    const int b  = blockIdx.z;
    const int m0 = blockIdx.y * 64;
    const int n0 = blockIdx.x * 64;
    const int tid = threadIdx.x;
    const int tx = tid & 15;     // cols n = tx*4..+3
    const int ty = tid >> 4;     // rows m = ty*4..+3

    float acc[4][4];
#pragma unroll
    for (int j = 0; j < 4; j++)
#pragma unroll
        for (int c = 0; c < 4; c++) acc[j][c] = 0.f;

    const float4* A4 = (const float4*)g_attn;
    const float4* B4 = (const float4*)values;

    for (int kt = 0; kt < VV; kt += 32) {
        // attn tile 64x32 (transposed)
#pragma unroll
        for (int i = 0; i < 2; i++) {
            int f = tid + i * 256;
            int m = f >> 3, k4 = f & 7;
            float4 a = A4[(size_t)(b * QQ + m0 + m) * (VV / 4) + (kt >> 2) + k4];
            as_s[(k4 * 4 + 0) * 68 + m] = a.x;
            as_s[(k4 * 4 + 1) * 68 + m] = a.y;
            as_s[(k4 * 4 + 2) * 68 + m] = a.z;
            as_s[(k4 * 4 + 3) * 68 + m] = a.w;
        }
        // values tile 32x64
#pragma unroll
        for (int i = 0; i < 2; i++) {
            int f = tid + i * 256;
            int k = f >> 4, n4 = f & 15;
            bs4[k * 16 + n4] = B4[(size_t)(b * VV + kt + k) * (HH / 4) + (n0 >> 2) + n4];
        }
        __syncthreads();

        const float4* as4 = (const float4*)as_s;
#pragma unroll
        for (int kk = 0; kk < 32; kk++) {
            float4 a = as4[kk * 17 + ty];
            float4 w = bs4[kk * 16 + tx];
            acc[0][0] += a.x * w.x; acc[0][1] += a.x * w.y; acc[0][2] += a.x * w.z; acc[0][3] += a.x * w.w;
            acc[1][0] += a.y * w.x; acc[1][1] += a.y * w.y; acc[1][2] += a.y * w.z; acc[1][3] += a.y * w.w;
            acc[2][0] += a.z * w.x; acc[2][1] += a.z * w.y; acc[2][2] += a.z * w.z; acc[2][3] += a.z * w.w;
            acc[3][0] += a.w * w.x; acc[3][1] += a.w * w.y; acc[3][2] += a.w * w.z; acc[3][3] += a.w * w.w;
        }
        __syncthreads();
    }

    float4* O4 = (float4*)out;
#pragma unroll
    for (int j = 0; j < 4; j++) {
        float4 o;
        o.x = acc[j][0]; o.y = acc[j][1]; o.z = acc[j][2]; o.w = acc[j][3];
        O4[(size_t)(b * QQ + m0 + ty * 4 + j) * (HH / 4) + (n0 >> 2) + tx] = o;
    }
}

// ---------------------------------------------------------------------------
extern "C" void kernel_launch(void* const* d_in, const int* in_sizes, int n_in,
                              void* d_out, int out_size)
{
    const float* queries = (const float*)d_in[0];   // [B,Q,H]
    const float* values  = (const float*)d_in[1];   // [B,V,H]
    const float* w1      = (const float*)d_in[2];   // [H,U]
    const float* w2      = (const float*)d_in[3];   // [H,U]
    const float* vvec    = (const float*)d_in[4];   // [U]
    float* out = (float*)d_out;                     // [B,Q,H]

    const int smemB = 4576 * 16;  // 73,216 bytes for score_kernel
    cudaFuncSetAttribute(score_kernel,
                         cudaFuncAttributeMaxDynamicSharedMemorySize, smemB);

    proj_kernel<<<144, 256>>>(queries, values, w1, w2);
    score_kernel<<<256, 256, smemB>>>(vvec);
    av_kernel<<<dim3(8, 4, 4), 256>>>(values, out);
}

// round 2
// speedup vs baseline: 1.1758x; 1.1758x over previous
#include <cuda_runtime.h>

#define BB 4
#define QQ 256
#define VV 2048
#define HH 512
#define UU 128

// Scratch (device globals: allocation-free rule)
__device__ float g_pq[BB * QQ * UU];     // [B,Q,U]
__device__ float g_pv[BB * VV * UU];     // [B,V,U]
__device__ float g_attn[BB * QQ * VV];   // [B,Q,V]

__device__ __forceinline__ float ftanh(float x) {
    float y;
    asm("tanh.approx.f32 %0, %1;" : "=f"(y) : "f"(x));
    return y;
}

// ---------------------------------------------------------------------------
// Kernel A: projections.
//   blocks [0,128):  pv = values[B*V,H] @ w2[H,U]
//   blocks [128,144): pq = queries[B*Q,H] @ w1[H,U]
// BM=64, BN=128(=U), BK=32. 256 threads, 8x4 register tile.
// W tile padded to stride 33 f4 (conflict-free), next-tile register prefetch.
// ---------------------------------------------------------------------------
__global__ __launch_bounds__(256) void proj_kernel(
    const float* __restrict__ queries, const float* __restrict__ values,
    const float* __restrict__ w1, const float* __restrict__ w2)
{
    __shared__ float  as_s[32 * 68];       // A tile transposed [k][m], pad 68
    __shared__ float4 ws4[32 * 33];        // W tile [k][n], stride 33 f4

    const float* A; const float* W; float* C; int mbase;
    if (blockIdx.x < 128) { A = values;  W = w2; C = g_pv; mbase = blockIdx.x * 64; }
    else                  { A = queries; W = w1; C = g_pq; mbase = (blockIdx.x - 128) * 64; }

    const int tid = threadIdx.x;
    const int tx = tid & 31;     // n-group: cols tx*4 .. tx*4+3
    const int ty = tid >> 5;     // m-group: rows ty*8 .. ty*8+7

    float acc[8][4];
#pragma unroll
    for (int j = 0; j < 8; j++)
#pragma unroll
        for (int c = 0; c < 4; c++) acc[j][c] = 0.f;

    const float4* A4 = (const float4*)A;
    const float4* W4 = (const float4*)W;

    // addressing helpers (constant per thread)
    const int am = tid >> 3;            // 0..31 (+32 for i=1)
    const int ak4 = tid & 7;
    const int wk = tid >> 5;            // 0..7 (+8 per i)
    const int wn4 = tid & 31;

    float4 pa[2], pw[4];
    // prologue: load k-tile 0
#pragma unroll
    for (int i = 0; i < 2; i++)
        pa[i] = A4[(size_t)(mbase + am + i * 32) * (HH / 4) + ak4];
#pragma unroll
    for (int i = 0; i < 4; i++)
        pw[i] = W4[(size_t)(wk + i * 8) * (UU / 4) + wn4];

    for (int kt = 0; kt < HH; kt += 32) {
        // store staged tile to SMEM
#pragma unroll
        for (int i = 0; i < 2; i++) {
            int m = am + i * 32;
            as_s[(ak4 * 4 + 0) * 68 + m] = pa[i].x;
            as_s[(ak4 * 4 + 1) * 68 + m] = pa[i].y;
            as_s[(ak4 * 4 + 2) * 68 + m] = pa[i].z;
            as_s[(ak4 * 4 + 3) * 68 + m] = pa[i].w;
        }
#pragma unroll
        for (int i = 0; i < 4; i++)
            ws4[(wk + i * 8) * 33 + wn4] = pw[i];

        // prefetch next k-tile
        if (kt + 32 < HH) {
            int ktn = kt + 32;
#pragma unroll
            for (int i = 0; i < 2; i++)
                pa[i] = A4[(size_t)(mbase + am + i * 32) * (HH / 4) + (ktn >> 2) + ak4];
#pragma unroll
            for (int i = 0; i < 4; i++)
                pw[i] = W4[(size_t)(ktn + wk + i * 8) * (UU / 4) + wn4];
        }
        __syncthreads();

        const float4* as4 = (const float4*)as_s;
#pragma unroll
        for (int kk = 0; kk < 32; kk++) {
            float4 a0 = as4[kk * 17 + ty * 2];
            float4 a1 = as4[kk * 17 + ty * 2 + 1];
            float4 b  = ws4[kk * 33 + tx];
            float av[8] = {a0.x, a0.y, a0.z, a0.w, a1.x, a1.y, a1.z, a1.w};
#pragma unroll
            for (int j = 0; j < 8; j++) {
                acc[j][0] += av[j] * b.x;
                acc[j][1] += av[j] * b.y;
                acc[j][2] += av[j] * b.z;
                acc[j][3] += av[j] * b.w;
            }
        }
        __syncthreads();
    }

    float4* C4 = (float4*)C;
#pragma unroll
    for (int j = 0; j < 8; j++) {
        float4 o;
        o.x = acc[j][0]; o.y = acc[j][1]; o.z = acc[j][2]; o.w = acc[j][3];
        C4[(size_t)(mbase + ty * 8 + j) * (UU / 4) + tx] = o;
    }
}

// ---------------------------------------------------------------------------
// Kernel B: scores + softmax -> attn. PERSISTENT, grid = 148 CTAs (37/batch).
// Each CTA: up to 7 consecutive q rows of one batch. pv staged in 32-row
// tiles (reused across all 7 q). Thread t: row r=t&31, u-group ug=t>>5
// (16 u's). Partials reduced via SMEM. Scores (7x2048) in SMEM; softmax at
// the end. Dynamic SMEM = 85,504 B.
// ---------------------------------------------------------------------------
#define SCORE_GRID 148
#define CPB 37            // CTAs per batch
#define NQMAX 7

__global__ __launch_bounds__(256) void score_kernel(const float* __restrict__ vvec)
{
    extern __shared__ float4 sm4[];
    float4* pvs4 = sm4;                       // 32*33 = 1056 f4
    float4* pqs4 = sm4 + 1056;                // 7*32 = 224 f4
    float4* vs4  = sm4 + 1056 + 224;          // 32 f4
    float*  scores = (float*)(sm4 + 1312);    // 7*2048 floats
    float*  sp     = scores + NQMAX * VV;     // 1792 floats (also softmax red)

    const int tid = threadIdx.x;
    const int b     = blockIdx.x / CPB;
    const int local = blockIdx.x % CPB;
    const int nq = (local < 34) ? 7 : 6;
    const int q0 = (local < 34) ? local * 7 : 238 + (local - 34) * 6;

    // Stage pq rows (nq x 128) and v vector
    {
        const float4* pqg4 = (const float4*)(g_pq + (size_t)(b * QQ + q0) * UU);
        if (tid < nq * 32) pqs4[tid] = pqg4[tid];
        if (tid < 32) vs4[tid] = ((const float4*)vvec)[tid];
    }

    const float4* pv4 = (const float4*)g_pv;
    const int r  = tid & 31;
    const int ug = tid >> 5;
    const int lrr = tid >> 5;       // pv-load row     (f = tid -> rr = tid>>5 + 8*i)
    const int lc  = tid & 31;       // pv-load col f4

    // prologue: prefetch pv tile vt=0 into registers
    float4 pf[4];
#pragma unroll
    for (int i = 0; i < 4; i++)
        pf[i] = pv4[(size_t)(b * VV + lrr + i * 8) * 32 + lc];

    __syncthreads();

    float4 vw[4];
#pragma unroll
    for (int u4 = 0; u4 < 4; u4++) vw[u4] = vs4[ug * 4 + u4];

    for (int vt = 0; vt < VV; vt += 32) {
        // store staged pv tile
#pragma unroll
        for (int i = 0; i < 4; i++)
            pvs4[(lrr + i * 8) * 33 + lc] = pf[i];
        // prefetch next tile
        if (vt + 32 < VV) {
#pragma unroll
            for (int i = 0; i < 4; i++)
                pf[i] = pv4[(size_t)(b * VV + vt + 32 + lrr + i * 8) * 32 + lc];
        }
        __syncthreads();

        float acc[NQMAX];
#pragma unroll
        for (int q = 0; q < NQMAX; q++) acc[q] = 0.f;

        const float4* prow = pvs4 + r * 33 + ug * 4;
#pragma unroll
        for (int u4 = 0; u4 < 4; u4++) {
            float4 p = prow[u4];
            float4 w = vw[u4];
#pragma unroll
            for (int q = 0; q < NQMAX; q++) {
                float4 qv = pqs4[q * 32 + ug * 4 + u4];
                acc[q] += ftanh(qv.x + p.x) * w.x;
                acc[q] += ftanh(qv.y + p.y) * w.y;
                acc[q] += ftanh(qv.z + p.z) * w.z;
                acc[q] += ftanh(qv.w + p.w) * w.w;
            }
        }
#pragma unroll
        for (int q = 0; q < NQMAX; q++) sp[q * 256 + tid] = acc[q];
        __syncthreads();

        if (tid < 224) {
            int q = tid >> 5, rr = tid & 31;
            float s = 0.f;
#pragma unroll
            for (int u = 0; u < 8; u++) s += sp[q * 256 + u * 32 + rr];
            scores[q * VV + vt + rr] = s;
        }
        __syncthreads();
    }

    // Softmax over V per q, write normalized attn
    float* red = sp;
    for (int qi = 0; qi < nq; qi++) {
        float* sc = scores + qi * VV;

        float m = -1e30f;
        for (int i = tid; i < VV; i += 256) m = fmaxf(m, sc[i]);
        red[tid] = m;
        __syncthreads();
        for (int s = 128; s > 0; s >>= 1) {
            if (tid < s) red[tid] = fmaxf(red[tid], red[tid + s]);
            __syncthreads();
        }
        m = red[0];
        __syncthreads();

        float lsum = 0.f;
        for (int i = tid; i < VV; i += 256) {
            float e = __expf(sc[i] - m);
            sc[i] = e;
            lsum += e;
        }
        red[tid] = lsum;
        __syncthreads();
        for (int s = 128; s > 0; s >>= 1) {
            if (tid < s) red[tid] += red[tid + s];
            __syncthreads();
        }
        float inv = 1.f / red[0];
        __syncthreads();

        float4* ag4 = (float4*)(g_attn + (size_t)(b * QQ + q0 + qi) * VV);
        const float4* sc4 = (const float4*)sc;
        for (int i = tid; i < VV / 4; i += 256) {
            float4 e = sc4[i];
            e.x *= inv; e.y *= inv; e.z *= inv; e.w *= inv;
            ag4[i] = e;
        }
        __syncthreads();
    }
}

// ---------------------------------------------------------------------------
// Kernel C: out[b] = attn[b] (256x2048) @ values[b] (2048x512).
// BM=64, BN=64, BK=32. 256 threads, 4x4 register tile. B tile padded to
// stride 17 f4 (conflict-free). Next-tile register prefetch.
// ---------------------------------------------------------------------------
__global__ __launch_bounds__(256) void av_kernel(
    const float* __restrict__ values, float* __restrict__ out)
{
    __shared__ float  as_s[32 * 68];   // attn tile transposed [k][m]
    __shared__ float4 bs4[32 * 17];    // values tile [k][n], stride 17 f4

    const int b  = blockIdx.z;
    const int m0 = blockIdx.y * 64;
    const int n0 = blockIdx.x * 64;
    const int tid = threadIdx.x;
    const int tx = tid & 15;     // cols n = tx*4..+3
    const int ty = tid >> 4;     // rows m = ty*4..+3

    float acc[4][4];
#pragma unroll
    for (int j = 0; j < 4; j++)
#pragma unroll
        for (int c = 0; c < 4; c++) acc[j][c] = 0.f;

    const float4* A4 = (const float4*)g_attn;
    const float4* B4 = (const float4*)values;

    const int am = tid >> 3;        // 0..31 (+32 for i=1)
    const int ak4 = tid & 7;
    const int bk = tid >> 4;        // 0..15 (+16 for i=1)
    const int bn4 = tid & 15;

    float4 pa[2], pb[2];
#pragma unroll
    for (int i = 0; i < 2; i++)
        pa[i] = A4[(size_t)(b * QQ + m0 + am + i * 32) * (VV / 4) + ak4];
#pragma unroll
    for (int i = 0; i < 2; i++)
        pb[i] = B4[(size_t)(b * VV + bk + i * 16) * (HH / 4) + (n0 >> 2) + bn4];

    for (int kt = 0; kt < VV; kt += 32) {
        // store staged tiles
#pragma unroll
        for (int i = 0; i < 2; i++) {
            int m = am + i * 32;
            as_s[(ak4 * 4 + 0) * 68 + m] = pa[i].x;
            as_s[(ak4 * 4 + 1) * 68 + m] = pa[i].y;
            as_s[(ak4 * 4 + 2) * 68 + m] = pa[i].z;
            as_s[(ak4 * 4 + 3) * 68 + m] = pa[i].w;
        }
#pragma unroll
        for (int i = 0; i < 2; i++)
            bs4[(bk + i * 16) * 17 + bn4] = pb[i];

        // prefetch next k-tile
        if (kt + 32 < VV) {
            int ktn = kt + 32;
#pragma unroll
            for (int i = 0; i < 2; i++)
                pa[i] = A4[(size_t)(b * QQ + m0 + am + i * 32) * (VV / 4) + (ktn >> 2) + ak4];
#pragma unroll
            for (int i = 0; i < 2; i++)
                pb[i] = B4[(size_t)(b * VV + ktn + bk + i * 16) * (HH / 4) + (n0 >> 2) + bn4];
        }
        __syncthreads();

        const float4* as4 = (const float4*)as_s;
#pragma unroll
        for (int kk = 0; kk < 32; kk++) {
            float4 a = as4[kk * 17 + ty];
            float4 w = bs4[kk * 17 + tx];
            acc[0][0] += a.x * w.x; acc[0][1] += a.x * w.y; acc[0][2] += a.x * w.z; acc[0][3] += a.x * w.w;
            acc[1][0] += a.y * w.x; acc[1][1] += a.y * w.y; acc[1][2] += a.y * w.z; acc[1][3] += a.y * w.w;
            acc[2][0] += a.z * w.x; acc[2][1] += a.z * w.y; acc[2][2] += a.z * w.z; acc[2][3] += a.z * w.w;
            acc[3][0] += a.w * w.x; acc[3][1] += a.w * w.y; acc[3][2] += a.w * w.z; acc[3][3] += a.w * w.w;
        }
        __syncthreads();
    }

    float4* O4 = (float4*)out;
#pragma unroll
    for (int j = 0; j < 4; j++) {
        float4 o;
        o.x = acc[j][0]; o.y = acc[j][1]; o.z = acc[j][2]; o.w = acc[j][3];
        O4[(size_t)(b * QQ + m0 + ty * 4 + j) * (HH / 4) + (n0 >> 2) + tx] = o;
    }
}

// ---------------------------------------------------------------------------
extern "C" void kernel_launch(void* const* d_in, const int* in_sizes, int n_in,
                              void* d_out, int out_size)
{
    const float* queries = (const float*)d_in[0];   // [B,Q,H]
    const float* values  = (const float*)d_in[1];   // [B,V,H]
    const float* w1      = (const float*)d_in[2];   // [H,U]
    const float* w2      = (const float*)d_in[3];   // [H,U]
    const float* vvec    = (const float*)d_in[4];   // [U]
    float* out = (float*)d_out;                     // [B,Q,H]

    const int smemB = 1312 * 16 + (NQMAX * VV + 1792) * 4;  // 85,504 B
    cudaFuncSetAttribute(score_kernel,
                         cudaFuncAttributeMaxDynamicSharedMemorySize, smemB);

    proj_kernel<<<144, 256>>>(queries, values, w1, w2);
    score_kernel<<<SCORE_GRID, 256, smemB>>>(vvec);
    av_kernel<<<dim3(8, 4, 4), 256>>>(values, out);
}

// round 3
// speedup vs baseline: 1.2137x; 1.0322x over previous
#include <cuda_runtime.h>

#define BB 4
#define QQ 256
#define VV 2048
#define HH 512
#define UU 128

// Scratch (device globals: allocation-free rule)
__device__ float g_pq[BB * QQ * UU];     // [B,Q,U]
__device__ float g_pv[BB * VV * UU];     // [B,V,U]
__device__ float g_attn[BB * QQ * VV];   // [B,Q,V]

__device__ __forceinline__ float ftanh(float x) {
    float y;
    asm("tanh.approx.f32 %0, %1;" : "=f"(y) : "f"(x));
    return y;
}

// Packed fp32x2 FMA (FFMA2) — ptxas never emits this from C++; PTX-only.
__device__ __forceinline__ unsigned long long fma2(
    unsigned long long a, unsigned long long b, unsigned long long c) {
    unsigned long long d;
    asm("fma.rn.f32x2 %0, %1, %2, %3;" : "=l"(d) : "l"(a), "l"(b), "l"(c));
    return d;
}
__device__ __forceinline__ unsigned long long bcast2(float x) {
    unsigned long long d;
    asm("mov.b64 %0, {%1, %1};" : "=l"(d) : "f"(x));
    return d;
}

// ---------------------------------------------------------------------------
// Kernel A: projections.
//   blocks [0,128):  pv = values[B*V,H] @ w2[H,U]
//   blocks [128,144): pq = queries[B*Q,H] @ w1[H,U]
// BM=64, BN=128(=U), BK=32. 256 threads, 8x4 register tile, FFMA2 inner loop.
// ---------------------------------------------------------------------------
__global__ __launch_bounds__(256) void proj_kernel(
    const float* __restrict__ queries, const float* __restrict__ values,
    const float* __restrict__ w1, const float* __restrict__ w2)
{
    __shared__ float  as_s[32 * 68];       // A tile transposed [k][m], pad 68
    __shared__ float4 ws4[32 * 33];        // W tile [k][n], stride 33 f4

    const float* A; const float* W; float* C; int mbase;
    if (blockIdx.x < 128) { A = values;  W = w2; C = g_pv; mbase = blockIdx.x * 64; }
    else                  { A = queries; W = w1; C = g_pq; mbase = (blockIdx.x - 128) * 64; }

    const int tid = threadIdx.x;
    const int tx = tid & 31;     // n-group: cols tx*4 .. tx*4+3
    const int ty = tid >> 5;     // m-group: rows ty*8 .. ty*8+7

    // acc pairs along n: accp[j][0]=(n0,n1), accp[j][1]=(n2,n3)
    unsigned long long accp[8][2];
#pragma unroll
    for (int j = 0; j < 8; j++) { accp[j][0] = 0ULL; accp[j][1] = 0ULL; }

    const float4* A4 = (const float4*)A;
    const float4* W4 = (const float4*)W;

    const int am = tid >> 3;            // 0..31 (+32 for i=1)
    const int ak4 = tid & 7;
    const int wk = tid >> 5;            // 0..7 (+8 per i)
    const int wn4 = tid & 31;

    float4 pa[2], pw[4];
#pragma unroll
    for (int i = 0; i < 2; i++)
        pa[i] = A4[(size_t)(mbase + am + i * 32) * (HH / 4) + ak4];
#pragma unroll
    for (int i = 0; i < 4; i++)
        pw[i] = W4[(size_t)(wk + i * 8) * (UU / 4) + wn4];

    for (int kt = 0; kt < HH; kt += 32) {
#pragma unroll
        for (int i = 0; i < 2; i++) {
            int m = am + i * 32;
            as_s[(ak4 * 4 + 0) * 68 + m] = pa[i].x;
            as_s[(ak4 * 4 + 1) * 68 + m] = pa[i].y;
            as_s[(ak4 * 4 + 2) * 68 + m] = pa[i].z;
            as_s[(ak4 * 4 + 3) * 68 + m] = pa[i].w;
        }
#pragma unroll
        for (int i = 0; i < 4; i++)
            ws4[(wk + i * 8) * 33 + wn4] = pw[i];

        if (kt + 32 < HH) {
            int ktn = kt + 32;
#pragma unroll
            for (int i = 0; i < 2; i++)
                pa[i] = A4[(size_t)(mbase + am + i * 32) * (HH / 4) + (ktn >> 2) + ak4];
#pragma unroll
            for (int i = 0; i < 4; i++)
                pw[i] = W4[(size_t)(ktn + wk + i * 8) * (UU / 4) + wn4];
        }
        __syncthreads();

        const float4* as4 = (const float4*)as_s;
        const ulonglong2* wsu = (const ulonglong2*)ws4;
#pragma unroll
        for (int kk = 0; kk < 32; kk++) {
            float4 a0 = as4[kk * 17 + ty * 2];       // warp-uniform (broadcast)
            float4 a1 = as4[kk * 17 + ty * 2 + 1];
            ulonglong2 bb = wsu[kk * 33 + tx];       // (n0,n1),(n2,n3) pairs
            float av[8] = {a0.x, a0.y, a0.z, a0.w, a1.x, a1.y, a1.z, a1.w};
#pragma unroll
            for (int j = 0; j < 8; j++) {
                unsigned long long a2 = bcast2(av[j]);
                accp[j][0] = fma2(a2, bb.x, accp[j][0]);
                accp[j][1] = fma2(a2, bb.y, accp[j][1]);
            }
        }
        __syncthreads();
    }

    float4* C4 = (float4*)C;
#pragma unroll
    for (int j = 0; j < 8; j++) {
        ulonglong2 t; t.x = accp[j][0]; t.y = accp[j][1];
        C4[(size_t)(mbase + ty * 8 + j) * (UU / 4) + tx] = *(float4*)&t;
    }
}

// ---------------------------------------------------------------------------
// Kernel B: scores + softmax -> attn. PERSISTENT, grid = 148 CTAs (37/batch).
// Each CTA: up to 7 consecutive q rows of one batch. pv staged in 32-row
// tiles (reused across all 7 q). MUFU.TANH-pipe-bound; left at fp32.
// Dynamic SMEM = 85,504 B.
// ---------------------------------------------------------------------------
#define SCORE_GRID 148
#define CPB 37            // CTAs per batch
#define NQMAX 7

__global__ __launch_bounds__(256) void score_kernel(const float* __restrict__ vvec)
{
    extern __shared__ float4 sm4[];
    float4* pvs4 = sm4;                       // 32*33 = 1056 f4
    float4* pqs4 = sm4 + 1056;                // 7*32 = 224 f4
    float4* vs4  = sm4 + 1056 + 224;          // 32 f4
    float*  scores = (float*)(sm4 + 1312);    // 7*2048 floats
    float*  sp     = scores + NQMAX * VV;     // 1792 floats (also softmax red)

    const int tid = threadIdx.x;
    const int b     = blockIdx.x / CPB;
    const int local = blockIdx.x % CPB;
    const int nq = (local < 34) ? 7 : 6;
    const int q0 = (local < 34) ? local * 7 : 238 + (local - 34) * 6;

    {
        const float4* pqg4 = (const float4*)(g_pq + (size_t)(b * QQ + q0) * UU);
        if (tid < nq * 32) pqs4[tid] = pqg4[tid];
        if (tid < 32) vs4[tid] = ((const float4*)vvec)[tid];
    }

    const float4* pv4 = (const float4*)g_pv;
    const int r  = tid & 31;
    const int ug = tid >> 5;
    const int lrr = tid >> 5;
    const int lc  = tid & 31;

    float4 pf[4];
#pragma unroll
    for (int i = 0; i < 4; i++)
        pf[i] = pv4[(size_t)(b * VV + lrr + i * 8) * 32 + lc];

    __syncthreads();

    float4 vw[4];
#pragma unroll
    for (int u4 = 0; u4 < 4; u4++) vw[u4] = vs4[ug * 4 + u4];

    for (int vt = 0; vt < VV; vt += 32) {
#pragma unroll
        for (int i = 0; i < 4; i++)
            pvs4[(lrr + i * 8) * 33 + lc] = pf[i];
        if (vt + 32 < VV) {
#pragma unroll
            for (int i = 0; i < 4; i++)
                pf[i] = pv4[(size_t)(b * VV + vt + 32 + lrr + i * 8) * 32 + lc];
        }
        __syncthreads();

        float acc[NQMAX];
#pragma unroll
        for (int q = 0; q < NQMAX; q++) acc[q] = 0.f;

        const float4* prow = pvs4 + r * 33 + ug * 4;
#pragma unroll
        for (int u4 = 0; u4 < 4; u4++) {
            float4 p = prow[u4];
            float4 w = vw[u4];
#pragma unroll
            for (int q = 0; q < NQMAX; q++) {
                float4 qv = pqs4[q * 32 + ug * 4 + u4];
                acc[q] += ftanh(qv.x + p.x) * w.x;
                acc[q] += ftanh(qv.y + p.y) * w.y;
                acc[q] += ftanh(qv.z + p.z) * w.z;
                acc[q] += ftanh(qv.w + p.w) * w.w;
            }
        }
#pragma unroll
        for (int q = 0; q < NQMAX; q++) sp[q * 256 + tid] = acc[q];
        __syncthreads();

        if (tid < 224) {
            int q = tid >> 5, rr = tid & 31;
            float s = 0.f;
#pragma unroll
            for (int u = 0; u < 8; u++) s += sp[q * 256 + u * 32 + rr];
            scores[q * VV + vt + rr] = s;
        }
        __syncthreads();
    }

    // Softmax over V per q, write normalized attn
    float* red = sp;
    for (int qi = 0; qi < nq; qi++) {
        float* sc = scores + qi * VV;

        float m = -1e30f;
        for (int i = tid; i < VV; i += 256) m = fmaxf(m, sc[i]);
        red[tid] = m;
        __syncthreads();
        for (int s = 128; s > 0; s >>= 1) {
            if (tid < s) red[tid] = fmaxf(red[tid], red[tid + s]);
            __syncthreads();
        }
        m = red[0];
        __syncthreads();

        float lsum = 0.f;
        for (int i = tid; i < VV; i += 256) {
            float e = __expf(sc[i] - m);
            sc[i] = e;
            lsum += e;
        }
        red[tid] = lsum;
        __syncthreads();
        for (int s = 128; s > 0; s >>= 1) {
            if (tid < s) red[tid] += red[tid + s];
            __syncthreads();
        }
        float inv = 1.f / red[0];
        __syncthreads();

        float4* ag4 = (float4*)(g_attn + (size_t)(b * QQ + q0 + qi) * VV);
        const float4* sc4 = (const float4*)sc;
        for (int i = tid; i < VV / 4; i += 256) {
            float4 e = sc4[i];
            e.x *= inv; e.y *= inv; e.z *= inv; e.w *= inv;
            ag4[i] = e;
        }
        __syncthreads();
    }
}

// ---------------------------------------------------------------------------
// Kernel C: out[b] = attn[b] (256x2048) @ values[b] (2048x512).
// BM=64, BN=64, BK=32. 256 threads, 4x4 register tile, FFMA2 inner loop.
// ---------------------------------------------------------------------------
__global__ __launch_bounds__(256) void av_kernel(
    const float* __restrict__ values, float* __restrict__ out)
{
    __shared__ float  as_s[32 * 68];   // attn tile transposed [k][m]
    __shared__ float4 bs4[32 * 17];    // values tile [k][n], stride 17 f4

    const int b  = blockIdx.z;
    const int m0 = blockIdx.y * 64;
    const int n0 = blockIdx.x * 64;
    const int tid = threadIdx.x;
    const int tx = tid & 15;     // cols n = tx*4..+3
    const int ty = tid >> 4;     // rows m = ty*4..+3

    // acc pairs along n: accp[j][0]=(n0,n1), accp[j][1]=(n2,n3)
    unsigned long long accp[4][2];
#pragma unroll
    for (int j = 0; j < 4; j++) { accp[j][0] = 0ULL; accp[j][1] = 0ULL; }

    const float4* A4 = (const float4*)g_attn;
    const float4* B4 = (const float4*)values;

    const int am = tid >> 3;        // 0..31 (+32 for i=1)
    const int ak4 = tid & 7;
    const int bk = tid >> 4;        // 0..15 (+16 for i=1)
    const int bn4 = tid & 15;

    float4 pa[2], pb[2];
#pragma unroll
    for (int i = 0; i < 2; i++)
        pa[i] = A4[(size_t)(b * QQ + m0 + am + i * 32) * (VV / 4) + ak4];
#pragma unroll
    for (int i = 0; i < 2; i++)
        pb[i] = B4[(size_t)(b * VV + bk + i * 16) * (HH / 4) + (n0 >> 2) + bn4];

    for (int kt = 0; kt < VV; kt += 32) {
#pragma unroll
        for (int i = 0; i < 2; i++) {
            int m = am + i * 32;
            as_s[(ak4 * 4 + 0) * 68 + m] = pa[i].x;
            as_s[(ak4 * 4 + 1) * 68 + m] = pa[i].y;
            as_s[(ak4 * 4 + 2) * 68 + m] = pa[i].z;
            as_s[(ak4 * 4 + 3) * 68 + m] = pa[i].w;
        }
#pragma unroll
        for (int i = 0; i < 2; i++)
            bs4[(bk + i * 16) * 17 + bn4] = pb[i];

        if (kt + 32 < VV) {
            int ktn = kt + 32;
#pragma unroll
            for (int i = 0; i < 2; i++)
                pa[i] = A4[(size_t)(b * QQ + m0 + am + i * 32) * (VV / 4) + (ktn >> 2) + ak4];
#pragma unroll
            for (int i = 0; i < 2; i++)
                pb[i] = B4[(size_t)(b * VV + ktn + bk + i * 16) * (HH / 4) + (n0 >> 2) + bn4];
        }
        __syncthreads();

        const float4* as4 = (const float4*)as_s;
        const ulonglong2* bsu = (const ulonglong2*)bs4;
#pragma unroll
        for (int kk = 0; kk < 32; kk++) {
            float4 a = as4[kk * 17 + ty];
            ulonglong2 w = bsu[kk * 17 + tx];
            float av[4] = {a.x, a.y, a.z, a.w};
#pragma unroll
            for (int j = 0; j < 4; j++) {
                unsigned long long a2 = bcast2(av[j]);
                accp[j][0] = fma2(a2, w.x, accp[j][0]);
                accp[j][1] = fma2(a2, w.y, accp[j][1]);
            }
        }
        __syncthreads();
    }

    float4* O4 = (float4*)out;
#pragma unroll
    for (int j = 0; j < 4; j++) {
        ulonglong2 t; t.x = accp[j][0]; t.y = accp[j][1];
        O4[(size_t)(b * QQ + m0 + ty * 4 + j) * (HH / 4) + (n0 >> 2) + tx] = *(float4*)&t;
    }
}

// ---------------------------------------------------------------------------
extern "C" void kernel_launch(void* const* d_in, const int* in_sizes, int n_in,
                              void* d_out, int out_size)
{
    const float* queries = (const float*)d_in[0];   // [B,Q,H]
    const float* values  = (const float*)d_in[1];   // [B,V,H]
    const float* w1      = (const float*)d_in[2];   // [H,U]
    const float* w2      = (const float*)d_in[3];   // [H,U]
    const float* vvec    = (const float*)d_in[4];   // [U]
    float* out = (float*)d_out;                     // [B,Q,H]

    const int smemB = 1312 * 16 + (NQMAX * VV + 1792) * 4;  // 85,504 B
    cudaFuncSetAttribute(score_kernel,
                         cudaFuncAttributeMaxDynamicSharedMemorySize, smemB);

    proj_kernel<<<144, 256>>>(queries, values, w1, w2);
    score_kernel<<<SCORE_GRID, 256, smemB>>>(vvec);
    av_kernel<<<dim3(8, 4, 4), 256>>>(values, out);
}

// round 5
// speedup vs baseline: 1.4626x; 1.2051x over previous
#include <cuda_runtime.h>

#define BB 4
#define QQ 256
#define VV 2048
#define HH 512
#define UU 128

typedef unsigned int       u32;
typedef unsigned long long u64;
typedef unsigned short     u16;

// Scratch (device globals: allocation-free rule)
__device__ float g_pq[BB * QQ * UU];          // [B,Q,U] fp32
__device__ float g_pv[BB * VV * UU];          // [B,V,U] fp32
__device__ u16   g_ahi[BB * QQ * VV];         // attn hi bf16 [B,Q,V]
__device__ u16   g_alo[BB * QQ * VV];         // attn lo bf16
__device__ u16   g_vthi[BB * HH * VV];        // values^T hi bf16 [B,H,V]
__device__ u16   g_vtlo[BB * HH * VV];        // values^T lo bf16

__device__ __forceinline__ float ftanh(float x) {
    float y; asm("tanh.approx.f32 %0, %1;" : "=f"(y) : "f"(x)); return y;
}
__device__ __forceinline__ u16 f2bf(float x) {
    u16 u; asm("cvt.rn.bf16.f32 %0, %1;" : "=h"(u) : "f"(x)); return u;
}
__device__ __forceinline__ float bf2f(u16 u) {
    float f; asm("cvt.f32.bf16 %0, %1;" : "=f"(f) : "h"(u)); return f;
}
__device__ __forceinline__ u32 smem_u32(const void* p) {
    u32 a;
    asm("{ .reg .u64 t; cvta.to.shared.u64 t, %1; cvt.u32.u64 %0, t; }"
        : "=r"(a) : "l"(p));
    return a;
}
__device__ __forceinline__ void ldsm4(u32& r0, u32& r1, u32& r2, u32& r3, u32 a) {
    asm volatile("ldmatrix.sync.aligned.m8n8.x4.shared.b16 {%0,%1,%2,%3}, [%4];"
                 : "=r"(r0), "=r"(r1), "=r"(r2), "=r"(r3) : "r"(a));
}
__device__ __forceinline__ void ldsm2(u32& r0, u32& r1, u32 a) {
    asm volatile("ldmatrix.sync.aligned.m8n8.x2.shared.b16 {%0,%1}, [%2];"
                 : "=r"(r0), "=r"(r1) : "r"(a));
}
__device__ __forceinline__ void mma16816(float* d, const u32* a, const u32* b) {
    asm volatile(
        "mma.sync.aligned.m16n8k16.row.col.f32.bf16.bf16.f32 "
        "{%0,%1,%2,%3}, {%4,%5,%6,%7}, {%8,%9}, {%0,%1,%2,%3};"
        : "+f"(d[0]), "+f"(d[1]), "+f"(d[2]), "+f"(d[3])
        : "r"(a[0]), "r"(a[1]), "r"(a[2]), "r"(a[3]), "r"(b[0]), "r"(b[1]));
}

// ---------------------------------------------------------------------------
// Kernel A: projections (fp32 FMA path, at pipe ceiling) + values^T bf16
// hi/lo emission for the tensor-core AV GEMM.
//   blocks [0,128):  pv = values @ w2, also emit vT hi/lo
//   blocks [128,144): pq = queries @ w1
// ---------------------------------------------------------------------------
__global__ __launch_bounds__(256) void proj_kernel(
    const float* __restrict__ queries, const float* __restrict__ values,
    const float* __restrict__ w1, const float* __restrict__ w2)
{
    __shared__ float  as_s[32 * 68];
    __shared__ float4 ws4[32 * 33];

    const bool isV = (blockIdx.x < 128);
    const float* A; const float* W; float* C; int mbase;
    if (isV) { A = values;  W = w2; C = g_pv; mbase = blockIdx.x * 64; }
    else     { A = queries; W = w1; C = g_pq; mbase = (blockIdx.x - 128) * 64; }

    const int tid = threadIdx.x;
    const int tx = tid & 31;
    const int ty = tid >> 5;

    float acc[8][4];
#pragma unroll
    for (int j = 0; j < 8; j++)
#pragma unroll
        for (int c = 0; c < 4; c++) acc[j][c] = 0.f;

    const float4* A4 = (const float4*)A;
    const float4* W4 = (const float4*)W;

    const int am = tid >> 3;
    const int ak4 = tid & 7;
    const int wk = tid >> 5;
    const int wn4 = tid & 31;

    // vT emission coords
    const int vb   = mbase >> 11;        // batch (VV=2048, 64|VV)
    const int vloc = mbase & (VV - 1);
    const int ek   = tid >> 3;           // 0..31 (k row in tile)
    const int eseg = tid & 7;            // 8-float segment

    float4 pa[2], pw[4];
#pragma unroll
    for (int i = 0; i < 2; i++)
        pa[i] = A4[(size_t)(mbase + am + i * 32) * (HH / 4) + ak4];
#pragma unroll
    for (int i = 0; i < 4; i++)
        pw[i] = W4[(size_t)(wk + i * 8) * (UU / 4) + wn4];

    for (int kt = 0; kt < HH; kt += 32) {
#pragma unroll
        for (int i = 0; i < 2; i++) {
            int m = am + i * 32;
            as_s[(ak4 * 4 + 0) * 68 + m] = pa[i].x;
            as_s[(ak4 * 4 + 1) * 68 + m] = pa[i].y;
            as_s[(ak4 * 4 + 2) * 68 + m] = pa[i].z;
            as_s[(ak4 * 4 + 3) * 68 + m] = pa[i].w;
        }
#pragma unroll
        for (int i = 0; i < 4; i++)
            ws4[(wk + i * 8) * 33 + wn4] = pw[i];

        if (kt + 32 < HH) {
            int ktn = kt + 32;
#pragma unroll
            for (int i = 0; i < 2; i++)
                pa[i] = A4[(size_t)(mbase + am + i * 32) * (HH / 4) + (ktn >> 2) + ak4];
#pragma unroll
            for (int i = 0; i < 4; i++)
                pw[i] = W4[(size_t)(ktn + wk + i * 8) * (UU / 4) + wn4];
        }
        __syncthreads();

        // Emit values^T bf16 hi/lo from the transposed tile:
        // as_s[kk*68 + m] = values[mbase+m][kt+kk]  ->  vT[h=kt+kk][v=mbase+m]
        if (isV) {
            const float* srow = as_s + ek * 68 + eseg * 8;
            float f[8];
#pragma unroll
            for (int j = 0; j < 8; j++) f[j] = srow[j];
            u16 hi[8], lo[8];
#pragma unroll
            for (int j = 0; j < 8; j++) {
                hi[j] = f2bf(f[j]);
                lo[j] = f2bf(f[j] - bf2f(hi[j]));
            }
            uint4 ph, pl;
            ph.x = (u32)hi[0] | ((u32)hi[1] << 16); ph.y = (u32)hi[2] | ((u32)hi[3] << 16);
            ph.z = (u32)hi[4] | ((u32)hi[5] << 16); ph.w = (u32)hi[6] | ((u32)hi[7] << 16);
            pl.x = (u32)lo[0] | ((u32)lo[1] << 16); pl.y = (u32)lo[2] | ((u32)lo[3] << 16);
            pl.z = (u32)lo[4] | ((u32)lo[5] << 16); pl.w = (u32)lo[6] | ((u32)lo[7] << 16);
            size_t off = (size_t)(vb * HH + kt + ek) * VV + vloc + eseg * 8;
            *(uint4*)(g_vthi + off) = ph;
            *(uint4*)(g_vtlo + off) = pl;
        }

        const float4* as4 = (const float4*)as_s;
#pragma unroll
        for (int kk = 0; kk < 32; kk++) {
            float4 a0 = as4[kk * 17 + ty * 2];
            float4 a1 = as4[kk * 17 + ty * 2 + 1];
            float4 b  = *(const float4*)&ws4[kk * 33 + tx];
            float av[8] = {a0.x, a0.y, a0.z, a0.w, a1.x, a1.y, a1.z, a1.w};
#pragma unroll
            for (int j = 0; j < 8; j++) {
                acc[j][0] += av[j] * b.x;
                acc[j][1] += av[j] * b.y;
                acc[j][2] += av[j] * b.z;
                acc[j][3] += av[j] * b.w;
            }
        }
        __syncthreads();
    }

    float4* C4 = (float4*)C;
#pragma unroll
    for (int j = 0; j < 8; j++) {
        float4 o;
        o.x = acc[j][0]; o.y = acc[j][1]; o.z = acc[j][2]; o.w = acc[j][3];
        C4[(size_t)(mbase + ty * 8 + j) * (UU / 4) + tx] = o;
    }
}

// ---------------------------------------------------------------------------
// Kernel B: scores + softmax -> attn (bf16 hi/lo). Persistent 148 CTAs.
// MUFU.TANH-bound.
// ---------------------------------------------------------------------------
#define SCORE_GRID 148
#define CPB 37
#define NQMAX 7

__global__ __launch_bounds__(256) void score_kernel(const float* __restrict__ vvec)
{
    extern __shared__ float4 sm4[];
    float4* pvs4 = sm4;                       // 32*33 f4
    float4* pqs4 = sm4 + 1056;                // 224 f4
    float4* vs4  = sm4 + 1056 + 224;          // 32 f4
    float*  scores = (float*)(sm4 + 1312);    // 7*2048 floats
    float*  sp     = scores + NQMAX * VV;     // 1792 floats

    const int tid = threadIdx.x;
    const int b     = blockIdx.x / CPB;
    const int local = blockIdx.x % CPB;
    const int nq = (local < 34) ? 7 : 6;
    const int q0 = (local < 34) ? local * 7 : 238 + (local - 34) * 6;

    {
        const float4* pqg4 = (const float4*)(g_pq + (size_t)(b * QQ + q0) * UU);
        if (tid < nq * 32) pqs4[tid] = pqg4[tid];
        if (tid < 32) vs4[tid] = ((const float4*)vvec)[tid];
    }

    const float4* pv4 = (const float4*)g_pv;
    const int r  = tid & 31;
    const int ug = tid >> 5;
    const int lrr = tid >> 5;
    const int lc  = tid & 31;

    float4 pf[4];
#pragma unroll
    for (int i = 0; i < 4; i++)
        pf[i] = pv4[(size_t)(b * VV + lrr + i * 8) * 32 + lc];

    __syncthreads();

    float4 vw[4];
#pragma unroll
    for (int u4 = 0; u4 < 4; u4++) vw[u4] = vs4[ug * 4 + u4];

    for (int vt = 0; vt < VV; vt += 32) {
#pragma unroll
        for (int i = 0; i < 4; i++)
            pvs4[(lrr + i * 8) * 33 + lc] = pf[i];
        if (vt + 32 < VV) {
#pragma unroll
            for (int i = 0; i < 4; i++)
                pf[i] = pv4[(size_t)(b * VV + vt + 32 + lrr + i * 8) * 32 + lc];
        }
        __syncthreads();

        float acc[NQMAX];
#pragma unroll
        for (int q = 0; q < NQMAX; q++) acc[q] = 0.f;

        const float4* prow = pvs4 + r * 33 + ug * 4;
#pragma unroll
        for (int u4 = 0; u4 < 4; u4++) {
            float4 p = prow[u4];
            float4 w = vw[u4];
#pragma unroll
            for (int q = 0; q < NQMAX; q++) {
                float4 qv = pqs4[q * 32 + ug * 4 + u4];
                acc[q] += ftanh(qv.x + p.x) * w.x;
                acc[q] += ftanh(qv.y + p.y) * w.y;
                acc[q] += ftanh(qv.z + p.z) * w.z;
                acc[q] += ftanh(qv.w + p.w) * w.w;
            }
        }
#pragma unroll
        for (int q = 0; q < NQMAX; q++) sp[q * 256 + tid] = acc[q];
        __syncthreads();

        if (tid < 224) {
            int q = tid >> 5, rr = tid & 31;
            float s = 0.f;
#pragma unroll
            for (int u = 0; u < 8; u++) s += sp[q * 256 + u * 32 + rr];
            scores[q * VV + vt + rr] = s;
        }
        __syncthreads();
    }

    // Softmax over V per q; write attn as bf16 hi/lo
    float* red = sp;
    for (int qi = 0; qi < nq; qi++) {
        float* sc = scores + qi * VV;

        float m = -1e30f;
        for (int i = tid; i < VV; i += 256) m = fmaxf(m, sc[i]);
        red[tid] = m;
        __syncthreads();
        for (int s = 128; s > 0; s >>= 1) {
            if (tid < s) red[tid] = fmaxf(red[tid], red[tid + s]);
            __syncthreads();
        }
        m = red[0];
        __syncthreads();

        float lsum = 0.f;
        for (int i = tid; i < VV; i += 256) {
            float e = __expf(sc[i] - m);
            sc[i] = e;
            lsum += e;
        }
        red[tid] = lsum;
        __syncthreads();
        for (int s = 128; s > 0; s >>= 1) {
            if (tid < s) red[tid] += red[tid + s];
            __syncthreads();
        }
        float inv = 1.f / red[0];
        __syncthreads();

        size_t rowoff = (size_t)(b * QQ + q0 + qi) * VV;
        const float4* sc4 = (const float4*)sc;
        for (int i = tid; i < VV / 4; i += 256) {
            float4 e = sc4[i];
            float f0 = e.x * inv, f1 = e.y * inv, f2 = e.z * inv, f3 = e.w * inv;
            u16 h0 = f2bf(f0), h1 = f2bf(f1), h2 = f2bf(f2), h3 = f2bf(f3);
            u16 l0 = f2bf(f0 - bf2f(h0)), l1 = f2bf(f1 - bf2f(h1));
            u16 l2 = f2bf(f2 - bf2f(h2)), l3 = f2bf(f3 - bf2f(h3));
            uint2 ph, pl;
            ph.x = (u32)h0 | ((u32)h1 << 16); ph.y = (u32)h2 | ((u32)h3 << 16);
            pl.x = (u32)l0 | ((u32)l1 << 16); pl.y = (u32)l2 | ((u32)l3 << 16);
            *(uint2*)(g_ahi + rowoff + i * 4) = ph;
            *(uint2*)(g_alo + rowoff + i * 4) = pl;
        }
        __syncthreads();
    }
}

// ---------------------------------------------------------------------------
// Kernel C: out[b] = attn[b] @ values[b] via mma.sync bf16 hi/lo (3 products).
// A = attn [Q,V] row-major (K=V); B = vT [H,V] "col-major" for row.col mma.
// CTA tile M=64(q) x N=64(h), BK=64. 8 warps = 2(m) x 4(n); warp tile 32x16.
// SMEM rows padded to 9x16B granules (144B) -> conflict-free ldmatrix.
// Grid (HH/64=8, QQ/64=4, BB=4) = 128 CTAs.
// ---------------------------------------------------------------------------
#define AV_STRIDE 72   // u16 per SMEM row (9 granules)

__global__ __launch_bounds__(256) void av_mma_kernel(float* __restrict__ out)
{
    __shared__ __align__(16) u16 sAh[64 * AV_STRIDE];
    __shared__ __align__(16) u16 sAl[64 * AV_STRIDE];
    __shared__ __align__(16) u16 sBh[64 * AV_STRIDE];
    __shared__ __align__(16) u16 sBl[64 * AV_STRIDE];

    const int tid = threadIdx.x;
    const int wid = tid >> 5;
    const int lane = tid & 31;

    const int b  = blockIdx.z;
    const int m0 = blockIdx.y * 64;
    const int n0 = blockIdx.x * 64;

    const int wm0 = (wid >> 2) * 32;   // warp m offset (0,32)
    const int wn0 = (wid & 3) * 16;    // warp n offset (0,16,32,48)

    // global load coords: 512 uint4 per tile, 2 per thread
    const int lrow = tid >> 3;         // 0..31 (+32)
    const int lg   = tid & 7;

    const uint4* gAh = (const uint4*)(g_ahi + (size_t)(b * QQ + m0) * VV);
    const uint4* gAl = (const uint4*)(g_alo + (size_t)(b * QQ + m0) * VV);
    const uint4* gBh = (const uint4*)(g_vthi + (size_t)(b * HH + n0) * VV);
    const uint4* gBl = (const uint4*)(g_vtlo + (size_t)(b * HH + n0) * VV);
    const int RW = VV / 8;             // uint4 per global row (256)

    float dacc[2][2][4];
#pragma unroll
    for (int i = 0; i < 2; i++)
#pragma unroll
        for (int j = 0; j < 2; j++)
#pragma unroll
            for (int c = 0; c < 4; c++) dacc[i][j][c] = 0.f;

    // prologue: chunk 0 -> regs
    uint4 pAh[2], pAl[2], pBh[2], pBl[2];
#pragma unroll
    for (int i = 0; i < 2; i++) {
        int row = lrow + i * 32;
        pAh[i] = gAh[(size_t)row * RW + lg];
        pAl[i] = gAl[(size_t)row * RW + lg];
        pBh[i] = gBh[(size_t)row * RW + lg];
        pBl[i] = gBl[(size_t)row * RW + lg];
    }

    const u32 bAh = smem_u32(sAh), bAl = smem_u32(sAl);
    const u32 bBh = smem_u32(sBh), bBl = smem_u32(sBl);

    // ldmatrix address components (byte offsets)
    const int arow = wm0 + (lane & 15);                 // A row for this lane
    const u32 aoff = (u32)(arow * 9 + (lane >> 4)) * 16;
    const int brow = wn0 + (lane & 7);
    const u32 boff = (u32)(brow * 9 + ((lane >> 3) & 1)) * 16;

    const int NCH = VV / 64;   // 32 chunks

    for (int c = 0; c < NCH; c++) {
        // store staged regs -> SMEM
#pragma unroll
        for (int i = 0; i < 2; i++) {
            int row = lrow + i * 32;
            u32 s = (u32)(row * 9 + lg) * 8;   // u16 index
            *(uint4*)(sAh + s) = pAh[i];
            *(uint4*)(sAl + s) = pAl[i];
            *(uint4*)(sBh + s) = pBh[i];
            *(uint4*)(sBl + s) = pBl[i];
        }
        __syncthreads();

        // prefetch next chunk
        if (c + 1 < NCH) {
            int g0 = (c + 1) * 8;
#pragma unroll
            for (int i = 0; i < 2; i++) {
                int row = lrow + i * 32;
                pAh[i] = gAh[(size_t)row * RW + g0 + lg];
                pAl[i] = gAl[(size_t)row * RW + g0 + lg];
                pBh[i] = gBh[(size_t)row * RW + g0 + lg];
                pBl[i] = gBl[(size_t)row * RW + g0 + lg];
            }
        }

#pragma unroll
        for (int kb = 0; kb < 4; kb++) {
            u32 kadd = (u32)(kb * 2) * 16;
            u32 ah[2][4], al[2][4], bh[2][2], bl[2][2];
#pragma unroll
            for (int mf = 0; mf < 2; mf++) {
                u32 ad = (u32)(mf * 16 * 9) * 16 + aoff + kadd;
                ldsm4(ah[mf][0], ah[mf][1], ah[mf][2], ah[mf][3], bAh + ad);
                ldsm4(al[mf][0], al[mf][1], al[mf][2], al[mf][3], bAl + ad);
            }
#pragma unroll
            for (int nf = 0; nf < 2; nf++) {
                u32 bd = (u32)(nf * 8 * 9) * 16 + boff + kadd;
                ldsm2(bh[nf][0], bh[nf][1], bBh + bd);
                ldsm2(bl[nf][0], bl[nf][1], bBl + bd);
            }
#pragma unroll
            for (int mf = 0; mf < 2; mf++)
#pragma unroll
                for (int nf = 0; nf < 2; nf++) {
                    mma16816(dacc[mf][nf], ah[mf], bh[nf]);
                    mma16816(dacc[mf][nf], ah[mf], bl[nf]);
                    mma16816(dacc[mf][nf], al[mf], bh[nf]);
                }
        }
        __syncthreads();
    }

    // epilogue: d frag layout: rows g, g+8; cols 2t, 2t+1
    const int g = lane >> 2;
    const int t = lane & 3;
#pragma unroll
    for (int mf = 0; mf < 2; mf++)
#pragma unroll
        for (int nf = 0; nf < 2; nf++) {
            int row = m0 + wm0 + mf * 16 + g;
            int col = n0 + wn0 + nf * 8 + t * 2;
            float2* o0 = (float2*)(out + (size_t)(b * QQ + row) * HH + col);
            float2* o1 = (float2*)(out + (size_t)(b * QQ + row + 8) * HH + col);
            float2 v0, v1;
            v0.x = dacc[mf][nf][0]; v0.y = dacc[mf][nf][1];
            v1.x = dacc[mf][nf][2]; v1.y = dacc[mf][nf][3];
            *o0 = v0;
            *o1 = v1;
        }
}

// ---------------------------------------------------------------------------
extern "C" void kernel_launch(void* const* d_in, const int* in_sizes, int n_in,
                              void* d_out, int out_size)
{
    const float* queries = (const float*)d_in[0];
    const float* values  = (const float*)d_in[1];
    const float* w1      = (const float*)d_in[2];
    const float* w2      = (const float*)d_in[3];
    const float* vvec    = (const float*)d_in[4];
    float* out = (float*)d_out;

    const int smemB = 1312 * 16 + (NQMAX * VV + 1792) * 4;  // 85,504 B
    cudaFuncSetAttribute(score_kernel,
                         cudaFuncAttributeMaxDynamicSharedMemorySize, smemB);

    proj_kernel<<<144, 256>>>(queries, values, w1, w2);
    score_kernel<<<SCORE_GRID, 256, smemB>>>(vvec);
    av_mma_kernel<<<dim3(HH / 64, QQ / 64, BB), 256>>>(out);
}

// round 6
// speedup vs baseline: 1.4796x; 1.0116x over previous
#include <cuda_runtime.h>

#define BB 4
#define QQ 256
#define VV 2048
#define HH 512
#define UU 128

typedef unsigned int       u32;
typedef unsigned long long u64;
typedef unsigned short     u16;

// Scratch (device globals: allocation-free rule)
__device__ float g_pq[BB * QQ * UU];          // [B,Q,U] fp32
__device__ float g_pv[BB * VV * UU];          // [B,V,U] fp32
__device__ u16   g_ahi[BB * QQ * VV];         // attn hi bf16 [B,Q,V]
__device__ u16   g_alo[BB * QQ * VV];         // attn lo bf16
__device__ u16   g_vthi[BB * HH * VV];        // values^T hi bf16 [B,H,V]
__device__ u16   g_vtlo[BB * HH * VV];        // values^T lo bf16
__device__ u16   g_vhi[BB * VV * HH];         // values hi bf16 [B,V,H]
__device__ u16   g_vlo[BB * VV * HH];         // values lo bf16
__device__ u16   g_qhi[BB * QQ * HH];         // queries hi bf16
__device__ u16   g_qlo[BB * QQ * HH];         // queries lo bf16
__device__ u16   g_w1thi[UU * HH];            // w1^T hi bf16 [U,H]
__device__ u16   g_w1tlo[UU * HH];
__device__ u16   g_w2thi[UU * HH];            // w2^T hi bf16 [U,H]
__device__ u16   g_w2tlo[UU * HH];

__device__ __forceinline__ float ftanh(float x) {
    float y; asm("tanh.approx.f32 %0, %1;" : "=f"(y) : "f"(x)); return y;
}
__device__ __forceinline__ u16 f2bf(float x) {
    u16 u; asm("cvt.rn.bf16.f32 %0, %1;" : "=h"(u) : "f"(x)); return u;
}
__device__ __forceinline__ float bf2f(u16 u) {
    float f; asm("cvt.f32.bf16 %0, %1;" : "=f"(f) : "h"(u)); return f;
}
__device__ __forceinline__ u32 smem_u32(const void* p) {
    u32 a;
    asm("{ .reg .u64 t; cvta.to.shared.u64 t, %1; cvt.u32.u64 %0, t; }"
        : "=r"(a) : "l"(p));
    return a;
}
__device__ __forceinline__ void ldsm4(u32& r0, u32& r1, u32& r2, u32& r3, u32 a) {
    asm volatile("ldmatrix.sync.aligned.m8n8.x4.shared.b16 {%0,%1,%2,%3}, [%4];"
                 : "=r"(r0), "=r"(r1), "=r"(r2), "=r"(r3) : "r"(a));
}
__device__ __forceinline__ void ldsm2(u32& r0, u32& r1, u32 a) {
    asm volatile("ldmatrix.sync.aligned.m8n8.x2.shared.b16 {%0,%1}, [%2];"
                 : "=r"(r0), "=r"(r1) : "r"(a));
}
__device__ __forceinline__ void mma16816(float* d, const u32* a, const u32* b) {
    asm volatile(
        "mma.sync.aligned.m16n8k16.row.col.f32.bf16.bf16.f32 "
        "{%0,%1,%2,%3}, {%4,%5,%6,%7}, {%8,%9}, {%0,%1,%2,%3};"
        : "+f"(d[0]), "+f"(d[1]), "+f"(d[2]), "+f"(d[3])
        : "r"(a[0]), "r"(a[1]), "r"(a[2]), "r"(a[3]), "r"(b[0]), "r"(b[1]));
}
// pack 2 floats -> (hi bf16 x2, lo bf16 x2)
__device__ __forceinline__ void pack2(float a, float b, u32& h, u32& l) {
    u16 ha = f2bf(a), hb = f2bf(b);
    u16 la = f2bf(a - bf2f(ha)), lb = f2bf(b - bf2f(hb));
    h = (u32)ha | ((u32)hb << 16);
    l = (u32)la | ((u32)lb << 16);
}

// ---------------------------------------------------------------------------
// Kernel 0: convert inputs to bf16 hi/lo in all layouts the MMA kernels need.
//   blocks [0,1024):    values 64x64 tiles -> g_vhi/g_vlo (row) + g_vthi/g_vtlo (transposed)
//   blocks [1024,1152): queries rowwise -> g_qhi/g_qlo
//   blocks [1152,1184): w1/w2 64x64 tiles -> g_w1t*/g_w2t* (transposed)
// ---------------------------------------------------------------------------
__global__ __launch_bounds__(256) void convert_kernel(
    const float* __restrict__ queries, const float* __restrict__ values,
    const float* __restrict__ w1, const float* __restrict__ w2)
{
    __shared__ float ts[64 * 65];
    const int bx = blockIdx.x, tid = threadIdx.x;

    if (bx < 1024) {
        const int b = bx >> 8, t = bx & 255;
        const int v0 = (t & 31) * 64, h0 = (t >> 5) * 64;
        const int r = tid >> 2, c0 = tid & 3;
        // stage 1: rowwise hi/lo + stage to SMEM
#pragma unroll
        for (int it = 0; it < 4; it++) {
            int c4 = c0 * 4 + it;    // 0..15 float4 per row
            float4 f = ((const float4*)(values + (size_t)(b * VV + v0 + r) * HH + h0))[c4];
            u32 h01, l01, h23, l23;
            pack2(f.x, f.y, h01, l01);
            pack2(f.z, f.w, h23, l23);
            size_t off = (size_t)(b * VV + v0 + r) * HH + h0 + c4 * 4;
            *(uint2*)(g_vhi + off) = make_uint2(h01, h23);
            *(uint2*)(g_vlo + off) = make_uint2(l01, l23);
            ts[r * 65 + c4 * 4 + 0] = f.x;
            ts[r * 65 + c4 * 4 + 1] = f.y;
            ts[r * 65 + c4 * 4 + 2] = f.z;
            ts[r * 65 + c4 * 4 + 3] = f.w;
        }
        __syncthreads();
        // stage 2: transposed hi/lo
        const int hr = tid >> 2, s0 = tid & 3;
#pragma unroll
        for (int it = 0; it < 4; it++) {
            int vs = s0 * 4 + it;    // 0..15, each covers 4 v
            float f0 = ts[(vs * 4 + 0) * 65 + hr];
            float f1 = ts[(vs * 4 + 1) * 65 + hr];
            float f2 = ts[(vs * 4 + 2) * 65 + hr];
            float f3 = ts[(vs * 4 + 3) * 65 + hr];
            u32 h01, l01, h23, l23;
            pack2(f0, f1, h01, l01);
            pack2(f2, f3, h23, l23);
            size_t off = (size_t)(b * HH + h0 + hr) * VV + v0 + vs * 4;
            *(uint2*)(g_vthi + off) = make_uint2(h01, h23);
            *(uint2*)(g_vtlo + off) = make_uint2(l01, l23);
        }
    } else if (bx < 1152) {
        // queries rowwise: 128 blocks x 4096 floats
        size_t base = (size_t)(bx - 1024) * 4096;
#pragma unroll
        for (int i = 0; i < 4; i++) {
            int idx = tid + i * 256;           // f4 index within block chunk
            float4 f = ((const float4*)queries)[base / 4 + idx];
            u32 h01, l01, h23, l23;
            pack2(f.x, f.y, h01, l01);
            pack2(f.z, f.w, h23, l23);
            size_t off = base + (size_t)idx * 4;
            *(uint2*)(g_qhi + off) = make_uint2(h01, h23);
            *(uint2*)(g_qlo + off) = make_uint2(l01, l23);
        }
    } else {
        // w transpose: [H=512, U=128] -> [U, H]; 16 tiles of 64x64 per matrix
        const int wb = bx - 1152;
        const float* W = (wb < 16) ? w1 : w2;
        u16* dh = (wb < 16) ? g_w1thi : g_w2thi;
        u16* dl = (wb < 16) ? g_w1tlo : g_w2tlo;
        const int t = wb & 15;
        const int h0 = (t & 7) * 64, u0 = (t >> 3) * 64;
        const int r = tid >> 2, c0 = tid & 3;
#pragma unroll
        for (int it = 0; it < 4; it++) {
            int c4 = c0 * 4 + it;    // 0..15
            float4 f = ((const float4*)(W + (size_t)(h0 + r) * UU + u0))[c4];
            ts[r * 65 + c4 * 4 + 0] = f.x;
            ts[r * 65 + c4 * 4 + 1] = f.y;
            ts[r * 65 + c4 * 4 + 2] = f.z;
            ts[r * 65 + c4 * 4 + 3] = f.w;
        }
        __syncthreads();
        const int ur = tid >> 2, s0 = tid & 3;
#pragma unroll
        for (int it = 0; it < 4; it++) {
            int hs = s0 * 4 + it;
            float f0 = ts[(hs * 4 + 0) * 65 + ur];
            float f1 = ts[(hs * 4 + 1) * 65 + ur];
            float f2 = ts[(hs * 4 + 2) * 65 + ur];
            float f3 = ts[(hs * 4 + 3) * 65 + ur];
            u32 h01, l01, h23, l23;
            pack2(f0, f1, h01, l01);
            pack2(f2, f3, h23, l23);
            size_t off = (size_t)(u0 + ur) * HH + h0 + hs * 4;
            *(uint2*)(dh + off) = make_uint2(h01, h23);
            *(uint2*)(dl + off) = make_uint2(l01, l23);
        }
    }
}

// ---------------------------------------------------------------------------
// Kernel A: projections via mma.sync bf16 hi/lo (3 products).
//   blocks [0,128):  pv = values @ w2  (M rows of g_vhi/g_vlo)
//   blocks [128,144): pq = queries @ w1
// CTA tile M=64 x N=128(=U), BK=64, K=512 (8 chunks). 8 warps = 2(m) x 4(n),
// warp tile 32x32. SMEM rows padded to 9x16B granules.
// ---------------------------------------------------------------------------
#define PJ_STRIDE 72

__global__ __launch_bounds__(256) void proj_tc_kernel()
{
    __shared__ __align__(16) u16 sAh[64 * PJ_STRIDE];
    __shared__ __align__(16) u16 sAl[64 * PJ_STRIDE];
    __shared__ __align__(16) u16 sBh[128 * PJ_STRIDE];
    __shared__ __align__(16) u16 sBl[128 * PJ_STRIDE];

    const int tid = threadIdx.x;
    const int wid = tid >> 5;
    const int lane = tid & 31;
    const int bx = blockIdx.x;

    const u16 *Ah, *Al, *Bh, *Bl; float* C; int m0;
    if (bx < 128) { Ah = g_vhi; Al = g_vlo; Bh = g_w2thi; Bl = g_w2tlo; C = g_pv; m0 = bx * 64; }
    else          { Ah = g_qhi; Al = g_qlo; Bh = g_w1thi; Bl = g_w1tlo; C = g_pq; m0 = (bx - 128) * 64; }

    const int wm0 = (wid >> 2) * 32;   // 0,32
    const int wn0 = (wid & 3) * 32;    // 0,32,64,96

    const int lrow = tid >> 3;         // 0..31
    const int lg   = tid & 7;

    const uint4* gAh = (const uint4*)(Ah + (size_t)m0 * HH);
    const uint4* gAl = (const uint4*)(Al + (size_t)m0 * HH);
    const uint4* gBh = (const uint4*)Bh;
    const uint4* gBl = (const uint4*)Bl;
    const int RW = HH / 8;             // 64 uint4 per row

    float dacc[2][4][4];
#pragma unroll
    for (int i = 0; i < 2; i++)
#pragma unroll
        for (int j = 0; j < 4; j++)
#pragma unroll
            for (int c = 0; c < 4; c++) dacc[i][j][c] = 0.f;

    uint4 pAh[2], pAl[2], pBh[4], pBl[4];
#pragma unroll
    for (int i = 0; i < 2; i++) {
        int row = lrow + i * 32;
        pAh[i] = gAh[(size_t)row * RW + lg];
        pAl[i] = gAl[(size_t)row * RW + lg];
    }
#pragma unroll
    for (int i = 0; i < 4; i++) {
        int row = lrow + i * 32;
        pBh[i] = gBh[(size_t)row * RW + lg];
        pBl[i] = gBl[(size_t)row * RW + lg];
    }

    const u32 bAh = smem_u32(sAh), bAl = smem_u32(sAl);
    const u32 bBh = smem_u32(sBh), bBl = smem_u32(sBl);

    const int arow = wm0 + (lane & 15);
    const u32 aoff = (u32)(arow * 9 + (lane >> 4)) * 16;
    const int brow = wn0 + (lane & 7);
    const u32 boff = (u32)(brow * 9 + ((lane >> 3) & 1)) * 16;

    const int NCH = HH / 64;   // 8

    for (int c = 0; c < NCH; c++) {
#pragma unroll
        for (int i = 0; i < 2; i++) {
            int row = lrow + i * 32;
            u32 s = (u32)(row * 9 + lg) * 8;
            *(uint4*)(sAh + s) = pAh[i];
            *(uint4*)(sAl + s) = pAl[i];
        }
#pragma unroll
        for (int i = 0; i < 4; i++) {
            int row = lrow + i * 32;
            u32 s = (u32)(row * 9 + lg) * 8;
            *(uint4*)(sBh + s) = pBh[i];
            *(uint4*)(sBl + s) = pBl[i];
        }
        __syncthreads();

        if (c + 1 < NCH) {
            int g0 = (c + 1) * 8;
#pragma unroll
            for (int i = 0; i < 2; i++) {
                int row = lrow + i * 32;
                pAh[i] = gAh[(size_t)row * RW + g0 + lg];
                pAl[i] = gAl[(size_t)row * RW + g0 + lg];
            }
#pragma unroll
            for (int i = 0; i < 4; i++) {
                int row = lrow + i * 32;
                pBh[i] = gBh[(size_t)row * RW + g0 + lg];
                pBl[i] = gBl[(size_t)row * RW + g0 + lg];
            }
        }

#pragma unroll
        for (int kb = 0; kb < 4; kb++) {
            u32 kadd = (u32)(kb * 2) * 16;
            u32 ah[2][4], al[2][4], bh[4][2], bl[4][2];
#pragma unroll
            for (int mf = 0; mf < 2; mf++) {
                u32 ad = (u32)(mf * 16 * 9) * 16 + aoff + kadd;
                ldsm4(ah[mf][0], ah[mf][1], ah[mf][2], ah[mf][3], bAh + ad);
                ldsm4(al[mf][0], al[mf][1], al[mf][2], al[mf][3], bAl + ad);
            }
#pragma unroll
            for (int nf = 0; nf < 4; nf++) {
                u32 bd = (u32)(nf * 8 * 9) * 16 + boff + kadd;
                ldsm2(bh[nf][0], bh[nf][1], bBh + bd);
                ldsm2(bl[nf][0], bl[nf][1], bBl + bd);
            }
#pragma unroll
            for (int mf = 0; mf < 2; mf++)
#pragma unroll
                for (int nf = 0; nf < 4; nf++) {
                    mma16816(dacc[mf][nf], ah[mf], bh[nf]);
                    mma16816(dacc[mf][nf], ah[mf], bl[nf]);
                    mma16816(dacc[mf][nf], al[mf], bh[nf]);
                }
        }
        __syncthreads();
    }

    const int g = lane >> 2;
    const int t = lane & 3;
#pragma unroll
    for (int mf = 0; mf < 2; mf++)
#pragma unroll
        for (int nf = 0; nf < 4; nf++) {
            int row = m0 + wm0 + mf * 16 + g;
            int col = wn0 + nf * 8 + t * 2;
            float2 v0, v1;
            v0.x = dacc[mf][nf][0]; v0.y = dacc[mf][nf][1];
            v1.x = dacc[mf][nf][2]; v1.y = dacc[mf][nf][3];
            *(float2*)(C + (size_t)row * UU + col) = v0;
            *(float2*)(C + (size_t)(row + 8) * UU + col) = v1;
        }
}

// ---------------------------------------------------------------------------
// Kernel B: scores + softmax -> attn (bf16 hi/lo). Persistent 148 CTAs.
// MUFU.TANH-bound (at floor).
// ---------------------------------------------------------------------------
#define SCORE_GRID 148
#define CPB 37
#define NQMAX 7

__global__ __launch_bounds__(256) void score_kernel(const float* __restrict__ vvec)
{
    extern __shared__ float4 sm4[];
    float4* pvs4 = sm4;                       // 32*33 f4
    float4* pqs4 = sm4 + 1056;                // 224 f4
    float4* vs4  = sm4 + 1056 + 224;          // 32 f4
    float*  scores = (float*)(sm4 + 1312);    // 7*2048 floats
    float*  sp     = scores + NQMAX * VV;     // 1792 floats

    const int tid = threadIdx.x;
    const int b     = blockIdx.x / CPB;
    const int local = blockIdx.x % CPB;
    const int nq = (local < 34) ? 7 : 6;
    const int q0 = (local < 34) ? local * 7 : 238 + (local - 34) * 6;

    {
        const float4* pqg4 = (const float4*)(g_pq + (size_t)(b * QQ + q0) * UU);
        if (tid < nq * 32) pqs4[tid] = pqg4[tid];
        if (tid < 32) vs4[tid] = ((const float4*)vvec)[tid];
    }

    const float4* pv4 = (const float4*)g_pv;
    const int r  = tid & 31;
    const int ug = tid >> 5;
    const int lrr = tid >> 5;
    const int lc  = tid & 31;

    float4 pf[4];
#pragma unroll
    for (int i = 0; i < 4; i++)
        pf[i] = pv4[(size_t)(b * VV + lrr + i * 8) * 32 + lc];

    __syncthreads();

    float4 vw[4];
#pragma unroll
    for (int u4 = 0; u4 < 4; u4++) vw[u4] = vs4[ug * 4 + u4];

    for (int vt = 0; vt < VV; vt += 32) {
#pragma unroll
        for (int i = 0; i < 4; i++)
            pvs4[(lrr + i * 8) * 33 + lc] = pf[i];
        if (vt + 32 < VV) {
#pragma unroll
            for (int i = 0; i < 4; i++)
                pf[i] = pv4[(size_t)(b * VV + vt + 32 + lrr + i * 8) * 32 + lc];
        }
        __syncthreads();

        float acc[NQMAX];
#pragma unroll
        for (int q = 0; q < NQMAX; q++) acc[q] = 0.f;

        const float4* prow = pvs4 + r * 33 + ug * 4;
#pragma unroll
        for (int u4 = 0; u4 < 4; u4++) {
            float4 p = prow[u4];
            float4 w = vw[u4];
#pragma unroll
            for (int q = 0; q < NQMAX; q++) {
                float4 qv = pqs4[q * 32 + ug * 4 + u4];
                acc[q] += ftanh(qv.x + p.x) * w.x;
                acc[q] += ftanh(qv.y + p.y) * w.y;
                acc[q] += ftanh(qv.z + p.z) * w.z;
                acc[q] += ftanh(qv.w + p.w) * w.w;
            }
        }
#pragma unroll
        for (int q = 0; q < NQMAX; q++) sp[q * 256 + tid] = acc[q];
        __syncthreads();

        if (tid < 224) {
            int q = tid >> 5, rr = tid & 31;
            float s = 0.f;
#pragma unroll
            for (int u = 0; u < 8; u++) s += sp[q * 256 + u * 32 + rr];
            scores[q * VV + vt + rr] = s;
        }
        __syncthreads();
    }

    float* red = sp;
    for (int qi = 0; qi < nq; qi++) {
        float* sc = scores + qi * VV;

        float m = -1e30f;
        for (int i = tid; i < VV; i += 256) m = fmaxf(m, sc[i]);
        red[tid] = m;
        __syncthreads();
        for (int s = 128; s > 0; s >>= 1) {
            if (tid < s) red[tid] = fmaxf(red[tid], red[tid + s]);
            __syncthreads();
        }
        m = red[0];
        __syncthreads();

        float lsum = 0.f;
        for (int i = tid; i < VV; i += 256) {
            float e = __expf(sc[i] - m);
            sc[i] = e;
            lsum += e;
        }
        red[tid] = lsum;
        __syncthreads();
        for (int s = 128; s > 0; s >>= 1) {
            if (tid < s) red[tid] += red[tid + s];
            __syncthreads();
        }
        float inv = 1.f / red[0];
        __syncthreads();

        size_t rowoff = (size_t)(b * QQ + q0 + qi) * VV;
        const float4* sc4 = (const float4*)sc;
        for (int i = tid; i < VV / 4; i += 256) {
            float4 e = sc4[i];
            float f0 = e.x * inv, f1 = e.y * inv, f2 = e.z * inv, f3 = e.w * inv;
            u32 h01, l01, h23, l23;
            pack2(f0, f1, h01, l01);
            pack2(f2, f3, h23, l23);
            *(uint2*)(g_ahi + rowoff + i * 4) = make_uint2(h01, h23);
            *(uint2*)(g_alo + rowoff + i * 4) = make_uint2(l01, l23);
        }
        __syncthreads();
    }
}

// ---------------------------------------------------------------------------
// Kernel C: out[b] = attn[b] @ values[b] via mma.sync bf16 hi/lo (3 products).
// CTA tile M=64(q) x N=64(h), BK=64. 8 warps = 2(m) x 4(n); warp tile 32x16.
// ---------------------------------------------------------------------------
#define AV_STRIDE 72

__global__ __launch_bounds__(256) void av_mma_kernel(float* __restrict__ out)
{
    __shared__ __align__(16) u16 sAh[64 * AV_STRIDE];
    __shared__ __align__(16) u16 sAl[64 * AV_STRIDE];
    __shared__ __align__(16) u16 sBh[64 * AV_STRIDE];
    __shared__ __align__(16) u16 sBl[64 * AV_STRIDE];

    const int tid = threadIdx.x;
    const int wid = tid >> 5;
    const int lane = tid & 31;

    const int b  = blockIdx.z;
    const int m0 = blockIdx.y * 64;
    const int n0 = blockIdx.x * 64;

    const int wm0 = (wid >> 2) * 32;
    const int wn0 = (wid & 3) * 16;

    const int lrow = tid >> 3;
    const int lg   = tid & 7;

    const uint4* gAh = (const uint4*)(g_ahi + (size_t)(b * QQ + m0) * VV);
    const uint4* gAl = (const uint4*)(g_alo + (size_t)(b * QQ + m0) * VV);
    const uint4* gBh = (const uint4*)(g_vthi + (size_t)(b * HH + n0) * VV);
    const uint4* gBl = (const uint4*)(g_vtlo + (size_t)(b * HH + n0) * VV);
    const int RW = VV / 8;

    float dacc[2][2][4];
#pragma unroll
    for (int i = 0; i < 2; i++)
#pragma unroll
        for (int j = 0; j < 2; j++)
#pragma unroll
            for (int c = 0; c < 4; c++) dacc[i][j][c] = 0.f;

    uint4 pAh[2], pAl[2], pBh[2], pBl[2];
#pragma unroll
    for (int i = 0; i < 2; i++) {
        int row = lrow + i * 32;
        pAh[i] = gAh[(size_t)row * RW + lg];
        pAl[i] = gAl[(size_t)row * RW + lg];
        pBh[i] = gBh[(size_t)row * RW + lg];
        pBl[i] = gBl[(size_t)row * RW + lg];
    }

    const u32 bAh = smem_u32(sAh), bAl = smem_u32(sAl);
    const u32 bBh = smem_u32(sBh), bBl = smem_u32(sBl);

    const int arow = wm0 + (lane & 15);
    const u32 aoff = (u32)(arow * 9 + (lane >> 4)) * 16;
    const int brow = wn0 + (lane & 7);
    const u32 boff = (u32)(brow * 9 + ((lane >> 3) & 1)) * 16;

    const int NCH = VV / 64;

    for (int c = 0; c < NCH; c++) {
#pragma unroll
        for (int i = 0; i < 2; i++) {
            int row = lrow + i * 32;
            u32 s = (u32)(row * 9 + lg) * 8;
            *(uint4*)(sAh + s) = pAh[i];
            *(uint4*)(sAl + s) = pAl[i];
            *(uint4*)(sBh + s) = pBh[i];
            *(uint4*)(sBl + s) = pBl[i];
        }
        __syncthreads();

        if (c + 1 < NCH) {
            int g0 = (c + 1) * 8;
#pragma unroll
            for (int i = 0; i < 2; i++) {
                int row = lrow + i * 32;
                pAh[i] = gAh[(size_t)row * RW + g0 + lg];
                pAl[i] = gAl[(size_t)row * RW + g0 + lg];
                pBh[i] = gBh[(size_t)row * RW + g0 + lg];
                pBl[i] = gBl[(size_t)row * RW + g0 + lg];
            }
        }

#pragma unroll
        for (int kb = 0; kb < 4; kb++) {
            u32 kadd = (u32)(kb * 2) * 16;
            u32 ah[2][4], al[2][4], bh[2][2], bl[2][2];
#pragma unroll
            for (int mf = 0; mf < 2; mf++) {
                u32 ad = (u32)(mf * 16 * 9) * 16 + aoff + kadd;
                ldsm4(ah[mf][0], ah[mf][1], ah[mf][2], ah[mf][3], bAh + ad);
                ldsm4(al[mf][0], al[mf][1], al[mf][2], al[mf][3], bAl + ad);
            }
#pragma unroll
            for (int nf = 0; nf < 2; nf++) {
                u32 bd = (u32)(nf * 8 * 9) * 16 + boff + kadd;
                ldsm2(bh[nf][0], bh[nf][1], bBh + bd);
                ldsm2(bl[nf][0], bl[nf][1], bBl + bd);
            }
#pragma unroll
            for (int mf = 0; mf < 2; mf++)
#pragma unroll
                for (int nf = 0; nf < 2; nf++) {
                    mma16816(dacc[mf][nf], ah[mf], bh[nf]);
                    mma16816(dacc[mf][nf], ah[mf], bl[nf]);
                    mma16816(dacc[mf][nf], al[mf], bh[nf]);
                }
        }
        __syncthreads();
    }

    const int g = lane >> 2;
    const int t = lane & 3;
#pragma unroll
    for (int mf = 0; mf < 2; mf++)
#pragma unroll
        for (int nf = 0; nf < 2; nf++) {
            int row = m0 + wm0 + mf * 16 + g;
            int col = n0 + wn0 + nf * 8 + t * 2;
            float2 v0, v1;
            v0.x = dacc[mf][nf][0]; v0.y = dacc[mf][nf][1];
            v1.x = dacc[mf][nf][2]; v1.y = dacc[mf][nf][3];
            *(float2*)(out + (size_t)(b * QQ + row) * HH + col) = v0;
            *(float2*)(out + (size_t)(b * QQ + row + 8) * HH + col) = v1;
        }
}

// ---------------------------------------------------------------------------
extern "C" void kernel_launch(void* const* d_in, const int* in_sizes, int n_in,
                              void* d_out, int out_size)
{
    const float* queries = (const float*)d_in[0];
    const float* values  = (const float*)d_in[1];
    const float* w1      = (const float*)d_in[2];
    const float* w2      = (const float*)d_in[3];
    const float* vvec    = (const float*)d_in[4];
    float* out = (float*)d_out;

    const int smemB = 1312 * 16 + (NQMAX * VV + 1792) * 4;  // 85,504 B
    cudaFuncSetAttribute(score_kernel,
                         cudaFuncAttributeMaxDynamicSharedMemorySize, smemB);

    convert_kernel<<<1184, 256>>>(queries, values, w1, w2);
    proj_tc_kernel<<<144, 256>>>();
    score_kernel<<<SCORE_GRID, 256, smemB>>>(vvec);
    av_mma_kernel<<<dim3(HH / 64, QQ / 64, BB), 256>>>(out);
}